// round 3
// baseline (speedup 1.0000x reference)
#include <cuda_runtime.h>
#include <cuda_bf16.h>

// out[b,p,h] = sum_{i,j} premise[b,p,i] * kernel[p,h,i,j] * hypothesis[b,h,j]
// B=8, P=96, H=96, D1=128, D2=128
//
// HBM-bound: the kernel tensor (604 MB fp32) is streamed exactly once.
// One CTA per (p,h); 128 threads, thread j owns column j of the 128x128 K tile.
// premise[:,p,:] staged in smem as [i][b] so each K element costs 2 broadcast
// LDS.128 + 8 FFMA. hypothesis applied in the epilogue before block reduction.

#define NB 8     // batch
#define NP 96
#define NH 96
#define ND 128   // D1 == D2

__global__ void __launch_bounds__(128, 8)
interaction_kernel(const float* __restrict__ premise,
                   const float* __restrict__ hyp,
                   const float* __restrict__ kern,
                   float* __restrict__ out)
{
    const int h   = blockIdx.x;   // 0..95
    const int p   = blockIdx.y;   // 0..95
    const int tid = threadIdx.x;  // 0..127  == column j

    __shared__ __align__(16) float pre_s[ND * NB];  // [i][b], 4 KB
    __shared__ float red[4][NB];

    // Stage premise[:, p, :] -> pre_s[i*8 + b]
#pragma unroll
    for (int r = 0; r < 8; r++) {
        int idx = tid + r * 128;          // 0..1023
        int i = idx >> 3;
        int b = idx & 7;
        pre_s[idx] = premise[((size_t)b * NP + p) * ND + i];
    }
    __syncthreads();

    // K tile base: kernel[p, h, 0, tid]
    const float* kp = kern + (((size_t)(p * NH + h)) << 14) + tid;

    float acc[NB];
#pragma unroll
    for (int b = 0; b < NB; b++) acc[b] = 0.0f;

    const float4* pre4 = reinterpret_cast<const float4*>(pre_s);

#pragma unroll 8
    for (int i = 0; i < ND; i++) {
        float  k  = kp[(size_t)i * ND];
        float4 p0 = pre4[i * 2 + 0];   // pre[i][0..3]  (warp broadcast)
        float4 p1 = pre4[i * 2 + 1];   // pre[i][4..7]
        acc[0] = fmaf(k, p0.x, acc[0]);
        acc[1] = fmaf(k, p0.y, acc[1]);
        acc[2] = fmaf(k, p0.z, acc[2]);
        acc[3] = fmaf(k, p0.w, acc[3]);
        acc[4] = fmaf(k, p1.x, acc[4]);
        acc[5] = fmaf(k, p1.y, acc[5]);
        acc[6] = fmaf(k, p1.z, acc[6]);
        acc[7] = fmaf(k, p1.w, acc[7]);
    }

    // Apply hypothesis[b, h, tid]
#pragma unroll
    for (int b = 0; b < NB; b++)
        acc[b] *= hyp[((size_t)b * NH + h) * ND + tid];

    // Warp reduction over j within each warp
#pragma unroll
    for (int off = 16; off; off >>= 1) {
#pragma unroll
        for (int b = 0; b < NB; b++)
            acc[b] += __shfl_down_sync(0xffffffffu, acc[b], off);
    }

    const int warp = tid >> 5;
    const int lane = tid & 31;
    if (lane == 0) {
#pragma unroll
        for (int b = 0; b < NB; b++) red[warp][b] = acc[b];
    }
    __syncthreads();

    if (tid < NB) {
        float s = red[0][tid] + red[1][tid] + red[2][tid] + red[3][tid];
        out[((size_t)tid * NP + p) * NH + h] = s;
    }
}

extern "C" void kernel_launch(void* const* d_in, const int* in_sizes, int n_in,
                              void* d_out, int out_size) {
    const float* premise = (const float*)d_in[0];  // (8, 96, 128)
    const float* hyp     = (const float*)d_in[1];  // (8, 96, 128)
    const float* kern    = (const float*)d_in[2];  // (96, 96, 128, 128)
    float* out = (float*)d_out;                    // (8, 96, 96)

    dim3 grid(NH, NP);
    interaction_kernel<<<grid, 128>>>(premise, hyp, kern, out);
}

// round 8
// speedup vs baseline: 1.1596x; 1.1596x over previous
#include <cuda_runtime.h>
#include <cuda_bf16.h>

// out[b,p,h] = sum_{i,j} premise[b,p,i] * kernel[p,h,i,j] * hypothesis[b,h,j]
// B=8, P=96, H=96, D1=D2=128
//
// HBM-bound (604 MB K tensor streamed once). One CTA per (p,h), 128 threads.
// Thread (warp w, lane l) owns columns 4l..4l+3 (float4 LDG.128) and rows
// i = w, w+4, ..., w+124. Batch pairs are processed with packed fma.rn.f32x2
// (sm_100+ native) so each 512B K row costs one warp ~16 FMA2 + 1 LDG.128 +
// 2 broadcast LDS.128 instead of 32 scalar FFMA + 12 L1 wavefronts.

#define NB 8
#define NP 96
#define NH 96
#define ND 128

using u64 = unsigned long long;

__device__ __forceinline__ u64 pack2(float lo, float hi) {
    u64 r;
    asm("mov.b64 %0, {%1, %2};" : "=l"(r) : "f"(lo), "f"(hi));
    return r;
}
__device__ __forceinline__ u64 fma2(u64 a, u64 b, u64 c) {
    u64 d;
    asm("fma.rn.f32x2 %0, %1, %2, %3;" : "=l"(d) : "l"(a), "l"(b), "l"(c));
    return d;
}
__device__ __forceinline__ void unpack2(u64 v, float& lo, float& hi) {
    asm("mov.b64 {%0, %1}, %2;" : "=f"(lo), "=f"(hi) : "l"(v));
}

__global__ void __launch_bounds__(128, 6)
interaction_kernel(const float* __restrict__ premise,
                   const float* __restrict__ hyp,
                   const float* __restrict__ kern,
                   float* __restrict__ out)
{
    const int h   = blockIdx.x;      // 0..95
    const int p   = blockIdx.y;      // 0..95
    const int tid = threadIdx.x;     // 0..127
    const int w   = tid >> 5;        // warp: row subset i ≡ w (mod 4)
    const int l   = tid & 31;        // lane: columns 4l..4l+3

    __shared__ __align__(16) float pre_s[ND * NB];  // [i][b], pairs contiguous
    __shared__ float red[4][NB];

    // Stage premise[:, p, :] -> pre_s[i*8 + b]
#pragma unroll
    for (int r = 0; r < 8; r++) {
        int idx = tid + r * 128;
        int i = idx >> 3;
        int b = idx & 7;
        pre_s[idx] = premise[((size_t)b * NP + p) * ND + i];
    }
    __syncthreads();

    // K tile: kernel[p,h,i,j]; this thread reads float4 at (i, 4l)
    const float4* kp = reinterpret_cast<const float4*>(
        kern + (((size_t)(p * NH + h)) << 14)) + l;   // row i -> kp[i*32]

    const ulonglong2* pre2 = reinterpret_cast<const ulonglong2*>(pre_s);

    // acc[bp][jj]: packed (b=2bp, b=2bp+1) accumulator for local column jj
    u64 acc[4][4];
#pragma unroll
    for (int bp = 0; bp < 4; bp++)
#pragma unroll
        for (int jj = 0; jj < 4; jj++) acc[bp][jj] = 0ull;

#pragma unroll 4
    for (int ii = 0; ii < 32; ii++) {
        const int i = w + 4 * ii;
        float4 kv = kp[i * 32];                 // LDG.128, 512B/row per warp
        ulonglong2 pa = pre2[i * 2 + 0];        // pre[i][0..3] as 2x f32x2
        ulonglong2 pb = pre2[i * 2 + 1];        // pre[i][4..7]
        u64 pr[4] = { pa.x, pa.y, pb.x, pb.y };
        u64 k2[4] = { pack2(kv.x, kv.x), pack2(kv.y, kv.y),
                      pack2(kv.z, kv.z), pack2(kv.w, kv.w) };
#pragma unroll
        for (int bp = 0; bp < 4; bp++)
#pragma unroll
            for (int jj = 0; jj < 4; jj++)
                acc[bp][jj] = fma2(k2[jj], pr[bp], acc[bp][jj]);
    }

    // Epilogue: fold hypothesis[b, h, 4l..4l+3], reduce over local columns
    float s[NB];
#pragma unroll
    for (int bp = 0; bp < 4; bp++) {
        float4 h0 = *reinterpret_cast<const float4*>(
            &hyp[((size_t)(2 * bp + 0) * NH + h) * ND + 4 * l]);
        float4 h1 = *reinterpret_cast<const float4*>(
            &hyp[((size_t)(2 * bp + 1) * NH + h) * ND + 4 * l]);
        u64 hs0 = pack2(h0.x, h1.x);
        u64 hs1 = pack2(h0.y, h1.y);
        u64 hs2 = pack2(h0.z, h1.z);
        u64 hs3 = pack2(h0.w, h1.w);
        u64 t = fma2(acc[bp][0], hs0, 0ull);
        t = fma2(acc[bp][1], hs1, t);
        t = fma2(acc[bp][2], hs2, t);
        t = fma2(acc[bp][3], hs3, t);
        unpack2(t, s[2 * bp], s[2 * bp + 1]);
    }

    // Reduce over 32 lanes (sums the j dimension)
#pragma unroll
    for (int off = 16; off; off >>= 1) {
#pragma unroll
        for (int b = 0; b < NB; b++)
            s[b] += __shfl_down_sync(0xffffffffu, s[b], off);
    }

    if (l == 0) {
#pragma unroll
        for (int b = 0; b < NB; b++) red[w][b] = s[b];
    }
    __syncthreads();

    // Sum the 4 warps' row-subsets
    if (tid < NB) {
        float v = red[0][tid] + red[1][tid] + red[2][tid] + red[3][tid];
        out[((size_t)tid * NP + p) * NH + h] = v;
    }
}

extern "C" void kernel_launch(void* const* d_in, const int* in_sizes, int n_in,
                              void* d_out, int out_size) {
    const float* premise = (const float*)d_in[0];  // (8, 96, 128)
    const float* hyp     = (const float*)d_in[1];  // (8, 96, 128)
    const float* kern    = (const float*)d_in[2];  // (96, 96, 128, 128)
    float* out = (float*)d_out;                    // (8, 96, 96)

    dim3 grid(NH, NP);
    interaction_kernel<<<grid, 128>>>(premise, hyp, kern, out);
}